// round 11
// baseline (speedup 1.0000x reference)
#include <cuda_runtime.h>
#include <cuda_fp16.h>
#include <math.h>
#include <stdint.h>

#define BB 16
#define SS_ 512
#define DD 1024
#define HH 16
#define LL 12
#define DKK 64
#define DFFN 4096
#define ROWS (BB*SS_)   // 8192

// ------------------------- scratch (static device memory) -------------------
__device__ float g_xn[ROWS * DD];     // LN output
__device__ float g_t [ROWS * DD];     // shared QKV projection t
__device__ float g_o [ROWS * DD];     // attention output
__device__ float g_h [ROWS * DFFN];   // FFN hidden

// fp16 transposed weights: [N][K] per layer
// wq: 12 x 1M | wo: 12 x 1M | w1: 12 x 4M | w2: 12 x 4M  = 120M halfs
#define WQ_OFF 0
#define WO_OFF (12u * 1024u * 1024u)
#define W1_OFF (24u * 1024u * 1024u)
#define W2_OFF (72u * 1024u * 1024u)
__device__ __half g_wh[120u * 1024u * 1024u];

__device__ __forceinline__ float to_tf32(float x) {
    uint32_t o;
    asm("cvt.rna.tf32.f32 %0, %1;" : "=r"(o) : "f"(x));
    return __uint_as_float(o);
}

__device__ __forceinline__ void mma_tf32(float c[4],
                                         uint32_t a0, uint32_t a1, uint32_t a2, uint32_t a3,
                                         uint32_t b0, uint32_t b1) {
    asm volatile(
        "mma.sync.aligned.m16n8k8.row.col.f32.tf32.tf32.f32 "
        "{%0,%1,%2,%3},{%4,%5,%6,%7},{%8,%9},{%0,%1,%2,%3};"
        : "+f"(c[0]), "+f"(c[1]), "+f"(c[2]), "+f"(c[3])
        : "r"(a0), "r"(a1), "r"(a2), "r"(a3), "r"(b0), "r"(b1));
}

__device__ __forceinline__ void mma_f16(float c[4],
                                        uint32_t a0, uint32_t a1, uint32_t a2, uint32_t a3,
                                        uint32_t b0, uint32_t b1) {
    asm volatile(
        "mma.sync.aligned.m16n8k16.row.col.f32.f16.f16.f32 "
        "{%0,%1,%2,%3},{%4,%5,%6,%7},{%8,%9},{%0,%1,%2,%3};"
        : "+f"(c[0]), "+f"(c[1]), "+f"(c[2]), "+f"(c[3])
        : "r"(a0), "r"(a1), "r"(a2), "r"(a3), "r"(b0), "r"(b1));
}

// ------------------------- weight transpose fp32[K][N] -> fp16[N][K] --------
// grid (N/32, K/32, L), block (32, 8)
__global__ void wtrans_kernel(const float* __restrict__ src, __half* __restrict__ dst,
                              int K, int N) {
    __shared__ float t[32][33];
    const size_t lsz = (size_t)K * N;
    const float* s = src + blockIdx.z * lsz;
    __half* d = dst + blockIdx.z * lsz;
    int n0 = blockIdx.x * 32, k0 = blockIdx.y * 32;
    int tx = threadIdx.x, ty = threadIdx.y;
    #pragma unroll
    for (int i = 0; i < 4; i++)
        t[ty + 8 * i][tx] = s[(size_t)(k0 + ty + 8 * i) * N + n0 + tx];
    __syncthreads();
    #pragma unroll
    for (int i = 0; i < 4; i++)
        d[(size_t)(n0 + ty + 8 * i) * K + k0 + tx] = __float2half_rn(t[tx][ty + 8 * i]);
}

// ------------------------- embedding + positional encoding ------------------
__global__ void embed_kernel(const int* __restrict__ masked,
                             const float* __restrict__ tok,
                             const float* __restrict__ seg,
                             float* __restrict__ x) {
    int bs = blockIdx.x;
    int s  = bs & (SS_ - 1);
    int id = masked[bs];
    const float* tp = tok + (size_t)id * DD;
    const float* sp = seg + DD;          // seg_emb[1]
    int j = threadIdx.x * 4;
    const float L = 0.0089944730328f;    // ln(10000)/1024
    float f0 = expf(-(float)j * L);
    float f1 = expf(-(float)(j + 2) * L);
    float a0 = (float)s * f0;
    float a1 = (float)s * f1;
    float4 tv = *(const float4*)(tp + j);
    float4 sv = *(const float4*)(sp + j);
    float4 r;
    r.x = tv.x + sinf(a0) + sv.x;
    r.y = tv.y + cosf(a0) + sv.y;
    r.z = tv.z + sinf(a1) + sv.z;
    r.w = tv.w + cosf(a1) + sv.w;
    *(float4*)(x + (size_t)bs * DD + j) = r;
}

// ------------------------- layernorm (warp-per-row) -------------------------
__global__ void ln_kernel(const float* __restrict__ x,
                          const float* __restrict__ gamma,
                          const float* __restrict__ beta,
                          float* __restrict__ y) {
    const int row  = blockIdx.x * 8 + (threadIdx.x >> 5);
    const int lane = threadIdx.x & 31;
    const float4* xp = (const float4*)(x + (size_t)row * DD);
    float4 v[8];
    float s = 0.f, q = 0.f;
    #pragma unroll
    for (int i = 0; i < 8; i++) {
        v[i] = xp[lane + 32 * i];
        s += v[i].x + v[i].y + v[i].z + v[i].w;
        q += v[i].x * v[i].x + v[i].y * v[i].y + v[i].z * v[i].z + v[i].w * v[i].w;
    }
    #pragma unroll
    for (int o = 16; o > 0; o >>= 1) {
        s += __shfl_xor_sync(0xffffffffu, s, o);
        q += __shfl_xor_sync(0xffffffffu, q, o);
    }
    float m = s * (1.0f / DD);
    float r = rsqrtf(q * (1.0f / DD) - m * m + 1e-5f);
    const float4* gp = (const float4*)gamma;
    const float4* bp = (const float4*)beta;
    float4* yp = (float4*)(y + (size_t)row * DD);
    #pragma unroll
    for (int i = 0; i < 8; i++) {
        float4 g = gp[lane + 32 * i];
        float4 b = bp[lane + 32 * i];
        float4 o4;
        o4.x = (v[i].x - m) * r * g.x + b.x;
        o4.y = (v[i].y - m) * r * g.y + b.y;
        o4.z = (v[i].z - m) * r * g.z + b.z;
        o4.w = (v[i].w - m) * r * g.w + b.w;
        yp[lane + 32 * i] = o4;
    }
}

// ------------------------- FP16 tensor-core GEMM -----------------------------
// C[M,N] = A[M,K](fp32, converted) * Bh[N,K](fp16 transposed), fp32 accum.
// CTA tile 128x128, k-tile 32 halfs, 8 warps, warp tile 64x32 via m16n8k16.
// smem: A/B tiles [128][40 halfs], double buffered (40 KB), stride-40 is
// conflict-free for fragment loads (banks 20g+8ks+t(+4) permute 0..31).
#define H_STRIDE 40
#define H_BUF (128 * H_STRIDE)
#define GEMM16_SMEM_BYTES (4 * H_BUF * 2)   // 2 ops x 2 bufs x halfs

template <int EPI>
__global__ __launch_bounds__(256, 2)
void gemm_f16_kernel(const float* __restrict__ A, const __half* __restrict__ Bh,
                     const float* __restrict__ bias, float* __restrict__ C,
                     int M, int N, int K) {
    extern __shared__ __half smh[];
    __half* As = smh;                 // [2][128][40]
    __half* Bs = smh + 2 * H_BUF;     // [2][128][40]

    const int tid  = threadIdx.x;
    const int lane = tid & 31;
    const int warp = tid >> 5;
    const int g = lane >> 2, tq = lane & 3;
    const int wm = (warp & 1) * 64;
    const int wn = (warp >> 1) * 32;
    const int bm = blockIdx.y, bn = blockIdx.x;

    const int row = tid >> 1;            // 0..127 (tile row for A / tile col-row for B)
    const int hs  = (tid & 1) * 16;      // 16-elem half-split of the 32-k tile
    const float*  Ag = A  + (size_t)(bm * 128 + row) * K + hs;
    const __half* Bg = Bh + (size_t)(bn * 128 + row) * K + hs;
    __half* Asw = As + row * H_STRIDE + hs;   // store target (buffer 0)
    __half* Bsw = Bs + row * H_STRIDE + hs;

    float4 av[4];
    uint4  bv[2];
    float acc[4][4][4];
    #pragma unroll
    for (int i = 0; i < 4; i++)
        #pragma unroll
        for (int j = 0; j < 4; j++)
            #pragma unroll
            for (int r = 0; r < 4; r++) acc[i][j][r] = 0.f;

    const int ntiles = K >> 5;

    // ---- prologue: tile 0 -> smem buf0; tile 1 -> regs; sync ----
    #pragma unroll
    for (int i = 0; i < 4; i++) av[i] = *(const float4*)(Ag + 4 * i);
    #pragma unroll
    for (int i = 0; i < 2; i++) bv[i] = *(const uint4*)(Bg + 8 * i);
    #pragma unroll
    for (int i = 0; i < 2; i++) {
        __half2 h0 = __floats2half2_rn(av[2*i].x,   av[2*i].y);
        __half2 h1 = __floats2half2_rn(av[2*i].z,   av[2*i].w);
        __half2 h2 = __floats2half2_rn(av[2*i+1].x, av[2*i+1].y);
        __half2 h3 = __floats2half2_rn(av[2*i+1].z, av[2*i+1].w);
        uint4 u;
        u.x = *(uint32_t*)&h0; u.y = *(uint32_t*)&h1;
        u.z = *(uint32_t*)&h2; u.w = *(uint32_t*)&h3;
        *(uint4*)(Asw + 8 * i) = u;
        *(uint4*)(Bsw + 8 * i) = bv[i];
    }
    if (ntiles > 1) {
        #pragma unroll
        for (int i = 0; i < 4; i++) av[i] = *(const float4*)(Ag + 32 + 4 * i);
        #pragma unroll
        for (int i = 0; i < 2; i++) bv[i] = *(const uint4*)(Bg + 32 + 8 * i);
    }
    __syncthreads();

    for (int kt = 0; kt < ntiles; kt++) {
        const int buf = kt & 1;

        // store tile kt+1 into the other buffer (overlaps compute)
        if (kt + 1 < ntiles) {
            __half* Ao = Asw + (buf ^ 1) * H_BUF;
            __half* Bo = Bsw + (buf ^ 1) * H_BUF;
            #pragma unroll
            for (int i = 0; i < 2; i++) {
                __half2 h0 = __floats2half2_rn(av[2*i].x,   av[2*i].y);
                __half2 h1 = __floats2half2_rn(av[2*i].z,   av[2*i].w);
                __half2 h2 = __floats2half2_rn(av[2*i+1].x, av[2*i+1].y);
                __half2 h3 = __floats2half2_rn(av[2*i+1].z, av[2*i+1].w);
                uint4 u;
                u.x = *(uint32_t*)&h0; u.y = *(uint32_t*)&h1;
                u.z = *(uint32_t*)&h2; u.w = *(uint32_t*)&h3;
                *(uint4*)(Ao + 8 * i) = u;
                *(uint4*)(Bo + 8 * i) = bv[i];
            }
        }
        // kick off gmem loads for tile kt+2
        if (kt + 2 < ntiles) {
            const float*  Agk = Ag + (kt + 2) * 32;
            const __half* Bgk = Bg + (kt + 2) * 32;
            #pragma unroll
            for (int i = 0; i < 4; i++) av[i] = *(const float4*)(Agk + 4 * i);
            #pragma unroll
            for (int i = 0; i < 2; i++) bv[i] = *(const uint4*)(Bgk + 8 * i);
        }

        // compute: 2 k16-steps x 16 mma
        const __half* Ab = As + buf * H_BUF;
        const __half* Bb = Bs + buf * H_BUF;
        #pragma unroll
        for (int ks = 0; ks < 2; ks++) {
            uint32_t af[4][4];
            uint32_t bf[4][2];
            #pragma unroll
            for (int mi = 0; mi < 4; mi++) {
                const __half* p = Ab + (wm + mi * 16 + g) * H_STRIDE + ks * 16 + 2 * tq;
                af[mi][0] = *(const uint32_t*)(p);
                af[mi][1] = *(const uint32_t*)(p + 8 * H_STRIDE);
                af[mi][2] = *(const uint32_t*)(p + 8);
                af[mi][3] = *(const uint32_t*)(p + 8 * H_STRIDE + 8);
            }
            #pragma unroll
            for (int nj = 0; nj < 4; nj++) {
                const __half* p = Bb + (wn + nj * 8 + g) * H_STRIDE + ks * 16 + 2 * tq;
                bf[nj][0] = *(const uint32_t*)(p);
                bf[nj][1] = *(const uint32_t*)(p + 8);
            }
            #pragma unroll
            for (int mi = 0; mi < 4; mi++)
                #pragma unroll
                for (int nj = 0; nj < 4; nj++)
                    mma_f16(acc[mi][nj], af[mi][0], af[mi][1], af[mi][2], af[mi][3],
                            bf[nj][0], bf[nj][1]);
        }

        if (kt + 1 < ntiles) __syncthreads();
    }

    // ---- epilogue ----
    const int row0 = bm * 128 + wm + g;
    const int col0 = bn * 128 + wn + 2 * tq;
    #pragma unroll
    for (int mi = 0; mi < 4; mi++) {
        #pragma unroll
        for (int nj = 0; nj < 4; nj++) {
            int c = col0 + nj * 8;
            float2 bvv = *(const float2*)(bias + c);
            #pragma unroll
            for (int half = 0; half < 2; half++) {
                int r = row0 + mi * 16 + half * 8;
                float* cp = C + (size_t)r * N + c;
                float v0 = acc[mi][nj][half * 2 + 0] + bvv.x;
                float v1 = acc[mi][nj][half * 2 + 1] + bvv.y;
                if (EPI == 1) { float2 rv = *(const float2*)cp; v0 += rv.x; v1 += rv.y; }
                if (EPI == 2) {
                    v0 = 0.5f * v0 * (1.0f + erff(v0 * 0.70710678118654752f));
                    v1 = 0.5f * v1 * (1.0f + erff(v1 * 0.70710678118654752f));
                }
                float2 w; w.x = v0; w.y = v1;
                *(float2*)cp = w;
            }
        }
    }
}

// ------------------------- tensor-core flash attention -----------------------
#define ATQ_STRIDE 76
#define ATKV_STRIDE 72
#define AQ_OFF   0
#define AP_OFF   (128 * ATQ_STRIDE)
#define AKV_OFF  (2 * 128 * ATQ_STRIDE)
#define ABIAS_OFF (AKV_OFF + 64 * ATKV_STRIDE)
#define ATT_SMEM_FLOATS (ABIAS_OFF + 512)

__global__ __launch_bounds__(256)
void attn_kernel(const float* __restrict__ t, const int* __restrict__ masked,
                 float* __restrict__ o) {
    extern __shared__ float sm[];
    float* QS    = sm + AQ_OFF;    // [128][76]
    float* PS    = sm + AP_OFF;    // [128][76]
    float* KV    = sm + AKV_OFF;   // [64][72]  (keys row-major)
    float* biasS = sm + ABIAS_OFF; // [512]

    const int qt = blockIdx.x, h = blockIdx.y, b = blockIdx.z;
    const int tid = threadIdx.x;
    const int lane = tid & 31, w = tid >> 5;
    const int lq = lane >> 2, la = lane & 3;
    const int qr = w * 16;                 // warp's q-row base within tile

    for (int i = tid; i < 512; i += 256)
        biasS[i] = (masked[b * 512 + i] == 1) ? -1e9f : 0.0f;

    {
        int row = tid >> 1;
        int c0  = (tid & 1) * 32;
        const float* qp = t + ((size_t)(b * 512 + qt * 128 + row)) * DD + h * 64 + c0;
        float* qs = QS + row * ATQ_STRIDE + c0;
        #pragma unroll
        for (int i = 0; i < 32; i += 4) {
            float4 v = *(const float4*)(qp + i);
            qs[i + 0] = to_tf32(v.x); qs[i + 1] = to_tf32(v.y);
            qs[i + 2] = to_tf32(v.z); qs[i + 3] = to_tf32(v.w);
        }
    }

    const float scale = 0.125f;
    float m0 = -1e30f, m1 = -1e30f, l0 = 0.f, l1 = 0.f;
    float oacc[8][4];
    #pragma unroll
    for (int nf = 0; nf < 8; nf++)
        #pragma unroll
        for (int r = 0; r < 4; r++) oacc[nf][r] = 0.f;

    for (int kt = 0; kt < 8; kt++) {
        __syncthreads();
        {
            int row = tid >> 2;
            int c0  = (tid & 3) * 16;
            const float* kp = t + ((size_t)(b * 512 + kt * 64 + row)) * DD + h * 64 + c0;
            float* ks = KV + row * ATKV_STRIDE + c0;
            #pragma unroll
            for (int i = 0; i < 16; i += 4) {
                float4 v = *(const float4*)(kp + i);
                ks[i + 0] = to_tf32(v.x); ks[i + 1] = to_tf32(v.y);
                ks[i + 2] = to_tf32(v.z); ks[i + 3] = to_tf32(v.w);
            }
        }
        __syncthreads();

        float s[8][4];
        #pragma unroll
        for (int nf = 0; nf < 8; nf++)
            #pragma unroll
            for (int r = 0; r < 4; r++) s[nf][r] = 0.f;

        #pragma unroll
        for (int kk = 0; kk < 8; kk++) {
            const float* ap = QS + (qr + lq) * ATQ_STRIDE + kk * 8 + la;
            uint32_t a0 = __float_as_uint(ap[0]);
            uint32_t a1 = __float_as_uint(ap[8 * ATQ_STRIDE]);
            uint32_t a2 = __float_as_uint(ap[4]);
            uint32_t a3 = __float_as_uint(ap[8 * ATQ_STRIDE + 4]);
            #pragma unroll
            for (int nf = 0; nf < 8; nf++) {
                const float* bp = KV + (nf * 8 + lq) * ATKV_STRIDE + kk * 8 + la;
                uint32_t b0 = __float_as_uint(bp[0]);
                uint32_t b1 = __float_as_uint(bp[4]);
                mma_tf32(s[nf], a0, a1, a2, a3, b0, b1);
            }
        }

        float tm0 = -1e30f, tm1 = -1e30f;
        #pragma unroll
        for (int nf = 0; nf < 8; nf++) {
            int c = kt * 64 + nf * 8 + 2 * la;
            float bv0 = biasS[c], bv1 = biasS[c + 1];
            s[nf][0] = s[nf][0] * scale + bv0;
            s[nf][1] = s[nf][1] * scale + bv1;
            s[nf][2] = s[nf][2] * scale + bv0;
            s[nf][3] = s[nf][3] * scale + bv1;
            tm0 = fmaxf(tm0, fmaxf(s[nf][0], s[nf][1]));
            tm1 = fmaxf(tm1, fmaxf(s[nf][2], s[nf][3]));
        }
        tm0 = fmaxf(tm0, __shfl_xor_sync(0xffffffffu, tm0, 1));
        tm0 = fmaxf(tm0, __shfl_xor_sync(0xffffffffu, tm0, 2));
        tm1 = fmaxf(tm1, __shfl_xor_sync(0xffffffffu, tm1, 1));
        tm1 = fmaxf(tm1, __shfl_xor_sync(0xffffffffu, tm1, 2));
        float mn0 = fmaxf(m0, tm0), mn1 = fmaxf(m1, tm1);
        float sc0 = __expf(m0 - mn0), sc1 = __expf(m1 - mn1);
        float ps0 = 0.f, ps1 = 0.f;
        float* pr0 = PS + (qr + lq) * ATQ_STRIDE + 2 * la;
        float* pr1 = PS + (qr + lq + 8) * ATQ_STRIDE + 2 * la;
        #pragma unroll
        for (int nf = 0; nf < 8; nf++) {
            float p0 = __expf(s[nf][0] - mn0);
            float p1 = __expf(s[nf][1] - mn0);
            float p2 = __expf(s[nf][2] - mn1);
            float p3 = __expf(s[nf][3] - mn1);
            ps0 += p0 + p1;
            ps1 += p2 + p3;
            pr0[nf * 8 + 0] = to_tf32(p0);
            pr0[nf * 8 + 1] = to_tf32(p1);
            pr1[nf * 8 + 0] = to_tf32(p2);
            pr1[nf * 8 + 1] = to_tf32(p3);
        }
        ps0 += __shfl_xor_sync(0xffffffffu, ps0, 1);
        ps0 += __shfl_xor_sync(0xffffffffu, ps0, 2);
        ps1 += __shfl_xor_sync(0xffffffffu, ps1, 1);
        ps1 += __shfl_xor_sync(0xffffffffu, ps1, 2);
        l0 = l0 * sc0 + ps0;
        l1 = l1 * sc1 + ps1;
        m0 = mn0; m1 = mn1;

        #pragma unroll
        for (int nf = 0; nf < 8; nf++) {
            oacc[nf][0] *= sc0; oacc[nf][1] *= sc0;
            oacc[nf][2] *= sc1; oacc[nf][3] *= sc1;
        }
        __syncwarp();

        #pragma unroll
        for (int kk = 0; kk < 8; kk++) {
            const float* ap = PS + (qr + lq) * ATQ_STRIDE + kk * 8 + la;
            uint32_t a0 = __float_as_uint(ap[0]);
            uint32_t a1 = __float_as_uint(ap[8 * ATQ_STRIDE]);
            uint32_t a2 = __float_as_uint(ap[4]);
            uint32_t a3 = __float_as_uint(ap[8 * ATQ_STRIDE + 4]);
            #pragma unroll
            for (int nf = 0; nf < 8; nf++) {
                const float* bp = KV + (kk * 8 + la) * ATKV_STRIDE + nf * 8 + lq;
                uint32_t b0 = __float_as_uint(bp[0]);
                uint32_t b1 = __float_as_uint(bp[4 * ATKV_STRIDE]);
                mma_tf32(oacc[nf], a0, a1, a2, a3, b0, b1);
            }
        }
    }

    float li0 = 1.0f / l0, li1 = 1.0f / l1;
    const size_t grow = (size_t)(b * 512 + qt * 128 + qr + lq);
    #pragma unroll
    for (int nf = 0; nf < 8; nf++) {
        int col = h * 64 + nf * 8 + 2 * la;
        float2 v0; v0.x = oacc[nf][0] * li0; v0.y = oacc[nf][1] * li0;
        float2 v1; v1.x = oacc[nf][2] * li1; v1.y = oacc[nf][3] * li1;
        *(float2*)(o + grow * DD + col) = v0;
        *(float2*)(o + (grow + 8) * DD + col) = v1;
    }
}

// ------------------------- host orchestration --------------------------------
extern "C" void kernel_launch(void* const* d_in, const int* in_sizes, int n_in,
                              void* d_out, int out_size) {
    const int*   masked = (const int*)  d_in[0];
    const float* tok    = (const float*)d_in[1];
    const float* seg    = (const float*)d_in[2];
    const float* ln1s   = (const float*)d_in[3];
    const float* ln1b   = (const float*)d_in[4];
    const float* wq     = (const float*)d_in[5];
    const float* bq     = (const float*)d_in[6];
    const float* wo     = (const float*)d_in[7];
    const float* bo     = (const float*)d_in[8];
    const float* ln2s   = (const float*)d_in[9];
    const float* ln2b   = (const float*)d_in[10];
    const float* w1     = (const float*)d_in[11];
    const float* b1     = (const float*)d_in[12];
    const float* w2     = (const float*)d_in[13];
    const float* b2     = (const float*)d_in[14];
    float* x = (float*)d_out;

    float *xn, *tt, *oo, *hh;
    __half* wh;
    cudaGetSymbolAddress((void**)&xn, g_xn);
    cudaGetSymbolAddress((void**)&tt, g_t);
    cudaGetSymbolAddress((void**)&oo, g_o);
    cudaGetSymbolAddress((void**)&hh, g_h);
    cudaGetSymbolAddress((void**)&wh, g_wh);

    const size_t ATT_SMEM = ATT_SMEM_FLOATS * sizeof(float);
    cudaFuncSetAttribute(attn_kernel, cudaFuncAttributeMaxDynamicSharedMemorySize,
                         (int)ATT_SMEM);

    // weight transposes (fp32 [K][N] -> fp16 [N][K], all layers)
    wtrans_kernel<<<dim3(DD / 32, DD / 32, LL), dim3(32, 8)>>>(wq, wh + WQ_OFF, DD, DD);
    wtrans_kernel<<<dim3(DD / 32, DD / 32, LL), dim3(32, 8)>>>(wo, wh + WO_OFF, DD, DD);
    wtrans_kernel<<<dim3(DFFN / 32, DD / 32, LL), dim3(32, 8)>>>(w1, wh + W1_OFF, DD, DFFN);
    wtrans_kernel<<<dim3(DD / 32, DFFN / 32, LL), dim3(32, 8)>>>(w2, wh + W2_OFF, DFFN, DD);

    embed_kernel<<<ROWS, 256>>>(masked, tok, seg, x);

    for (int l = 0; l < LL; l++) {
        const __half* wql = wh + WQ_OFF + (size_t)l * DD * DD;
        const __half* wol = wh + WO_OFF + (size_t)l * DD * DD;
        const __half* w1l = wh + W1_OFF + (size_t)l * DD * DFFN;
        const __half* w2l = wh + W2_OFF + (size_t)l * DFFN * DD;

        ln_kernel<<<ROWS / 8, 256>>>(x, ln1s + l * DD, ln1b + l * DD, xn);
        gemm_f16_kernel<0><<<dim3(DD / 128, ROWS / 128), 256, GEMM16_SMEM_BYTES>>>(
            xn, wql, bq + l * DD, tt, ROWS, DD, DD);
        attn_kernel<<<dim3(4, HH, BB), 256, ATT_SMEM>>>(tt, masked, oo);
        gemm_f16_kernel<1><<<dim3(DD / 128, ROWS / 128), 256, GEMM16_SMEM_BYTES>>>(
            oo, wol, bo + l * DD, x, ROWS, DD, DD);
        ln_kernel<<<ROWS / 8, 256>>>(x, ln2s + l * DD, ln2b + l * DD, xn);
        gemm_f16_kernel<2><<<dim3(DFFN / 128, ROWS / 128), 256, GEMM16_SMEM_BYTES>>>(
            xn, w1l, b1 + l * DFFN, hh, ROWS, DFFN, DD);
        gemm_f16_kernel<1><<<dim3(DD / 128, ROWS / 128), 256, GEMM16_SMEM_BYTES>>>(
            hh, w2l, b2 + l * DD, x, ROWS, DD, DFFN);
    }
}

// round 14
// speedup vs baseline: 2.1179x; 2.1179x over previous
#include <cuda_runtime.h>
#include <cuda_fp16.h>
#include <math.h>
#include <stdint.h>

#define BB 16
#define SS_ 512
#define DD 1024
#define HH 16
#define LL 12
#define DKK 64
#define DFFN 4096
#define ROWS (BB*SS_)   // 8192

// ------------------------- scratch (static device memory) -------------------
__device__ float  g_t [ROWS * DD];     // QKV projection t (fp32, feeds attn)
__device__ __half g_xh[ROWS * DD];     // LN output (fp16, GEMM A)
__device__ __half g_oh[ROWS * DD];     // attention output (fp16, GEMM A)
__device__ __half g_hh[ROWS * DFFN];   // FFN hidden (fp16, GEMM A)

// fp16 transposed weights [N][K] per layer
#define WQ_OFF 0
#define WO_OFF (12u * 1024u * 1024u)
#define W1_OFF (24u * 1024u * 1024u)
#define W2_OFF (72u * 1024u * 1024u)
__device__ __half g_wh[120u * 1024u * 1024u];

__device__ __forceinline__ float to_tf32(float x) {
    uint32_t o;
    asm("cvt.rna.tf32.f32 %0, %1;" : "=r"(o) : "f"(x));
    return __uint_as_float(o);
}

__device__ __forceinline__ void mma_tf32(float c[4],
                                         uint32_t a0, uint32_t a1, uint32_t a2, uint32_t a3,
                                         uint32_t b0, uint32_t b1) {
    asm volatile(
        "mma.sync.aligned.m16n8k8.row.col.f32.tf32.tf32.f32 "
        "{%0,%1,%2,%3},{%4,%5,%6,%7},{%8,%9},{%0,%1,%2,%3};"
        : "+f"(c[0]), "+f"(c[1]), "+f"(c[2]), "+f"(c[3])
        : "r"(a0), "r"(a1), "r"(a2), "r"(a3), "r"(b0), "r"(b1));
}

__device__ __forceinline__ void mma_f16(float c[4],
                                        uint32_t a0, uint32_t a1, uint32_t a2, uint32_t a3,
                                        uint32_t b0, uint32_t b1) {
    asm volatile(
        "mma.sync.aligned.m16n8k16.row.col.f32.f16.f16.f32 "
        "{%0,%1,%2,%3},{%4,%5,%6,%7},{%8,%9},{%0,%1,%2,%3};"
        : "+f"(c[0]), "+f"(c[1]), "+f"(c[2]), "+f"(c[3])
        : "r"(a0), "r"(a1), "r"(a2), "r"(a3), "r"(b0), "r"(b1));
}

__device__ __forceinline__ void cp_async16(uint32_t saddr, const void* gptr) {
    asm volatile("cp.async.cg.shared.global [%0], [%1], 16;"
                 :: "r"(saddr), "l"(gptr) : "memory");
}
#define CP_COMMIT() asm volatile("cp.async.commit_group;" ::: "memory")
#define CP_WAIT1()  asm volatile("cp.async.wait_group 1;" ::: "memory")

// ------------------------- weight transpose fp32[K][N] -> fp16[N][K] --------
__global__ void wtrans_kernel(const float* __restrict__ src, __half* __restrict__ dst,
                              int K, int N) {
    __shared__ float t[32][33];
    const size_t lsz = (size_t)K * N;
    const float* s = src + blockIdx.z * lsz;
    __half* d = dst + blockIdx.z * lsz;
    int n0 = blockIdx.x * 32, k0 = blockIdx.y * 32;
    int tx = threadIdx.x, ty = threadIdx.y;
    #pragma unroll
    for (int i = 0; i < 4; i++)
        t[ty + 8 * i][tx] = s[(size_t)(k0 + ty + 8 * i) * N + n0 + tx];
    __syncthreads();
    #pragma unroll
    for (int i = 0; i < 4; i++)
        d[(size_t)(n0 + ty + 8 * i) * K + k0 + tx] = __float2half_rn(t[tx][ty + 8 * i]);
}

// ------------------------- embedding + positional encoding ------------------
__global__ void embed_kernel(const int* __restrict__ masked,
                             const float* __restrict__ tok,
                             const float* __restrict__ seg,
                             float* __restrict__ x) {
    int bs = blockIdx.x;
    int s  = bs & (SS_ - 1);
    int id = masked[bs];
    const float* tp = tok + (size_t)id * DD;
    const float* sp = seg + DD;          // seg_emb[1]
    int j = threadIdx.x * 4;
    const float L = 0.0089944730328f;    // ln(10000)/1024
    float f0 = expf(-(float)j * L);
    float f1 = expf(-(float)(j + 2) * L);
    float a0 = (float)s * f0;
    float a1 = (float)s * f1;
    float4 tv = *(const float4*)(tp + j);
    float4 sv = *(const float4*)(sp + j);
    float4 r;
    r.x = tv.x + sinf(a0) + sv.x;
    r.y = tv.y + cosf(a0) + sv.y;
    r.z = tv.z + sinf(a1) + sv.z;
    r.w = tv.w + cosf(a1) + sv.w;
    *(float4*)(x + (size_t)bs * DD + j) = r;
}

// ------------------------- layernorm (warp-per-row, fp16 out) ---------------
__global__ void ln_kernel(const float* __restrict__ x,
                          const float* __restrict__ gamma,
                          const float* __restrict__ beta,
                          __half* __restrict__ y) {
    const int row  = blockIdx.x * 8 + (threadIdx.x >> 5);
    const int lane = threadIdx.x & 31;
    const float4* xp = (const float4*)(x + (size_t)row * DD);
    float4 v[8];
    float s = 0.f, q = 0.f;
    #pragma unroll
    for (int i = 0; i < 8; i++) {
        v[i] = xp[lane + 32 * i];
        s += v[i].x + v[i].y + v[i].z + v[i].w;
        q += v[i].x * v[i].x + v[i].y * v[i].y + v[i].z * v[i].z + v[i].w * v[i].w;
    }
    #pragma unroll
    for (int o = 16; o > 0; o >>= 1) {
        s += __shfl_xor_sync(0xffffffffu, s, o);
        q += __shfl_xor_sync(0xffffffffu, q, o);
    }
    float m = s * (1.0f / DD);
    float r = rsqrtf(q * (1.0f / DD) - m * m + 1e-5f);
    const float4* gp = (const float4*)gamma;
    const float4* bp = (const float4*)beta;
    __half2* yp = (__half2*)(y + (size_t)row * DD);
    #pragma unroll
    for (int i = 0; i < 8; i++) {
        float4 g = gp[lane + 32 * i];
        float4 b = bp[lane + 32 * i];
        int e = (lane + 32 * i) * 2;
        yp[e + 0] = __floats2half2_rn((v[i].x - m) * r * g.x + b.x,
                                      (v[i].y - m) * r * g.y + b.y);
        yp[e + 1] = __floats2half2_rn((v[i].z - m) * r * g.z + b.z,
                                      (v[i].w - m) * r * g.w + b.w);
    }
}

// ------------------------- FP16 tensor-core GEMM (cp.async 3-stage) ----------
// C[M,N] = Ah[M,K](fp16) * Bh[N,K](fp16 transposed), fp32 accum.
// CTA tile 128x128, k-tile 32 halfs, 8 warps, warp tile 64x32 via m16n8k16.
// smem: per stage A[128][40]+B[128][40] halfs = 20480 B; 3 stages = 61440 B.
// EPI: 0 = bias -> fp32; 1 = bias + residual fp32 in-place; 2 = bias+GELU -> fp16.
#define H_STRIDE 40
#define STAGE_BYTES 20480
#define GEMM16_SMEM_BYTES (3 * STAGE_BYTES)

template <int EPI>
__global__ __launch_bounds__(256, 2)
void gemm_f16_kernel(const __half* __restrict__ Ah, const __half* __restrict__ Bh,
                     const float* __restrict__ bias, void* __restrict__ Cv,
                     int M, int N, int K) {
    extern __shared__ __half smh[];
    const int tid  = threadIdx.x;
    const int lane = tid & 31;
    const int warp = tid >> 5;
    const int g = lane >> 2, tq = lane & 3;
    const int wm = (warp & 1) * 64;
    const int wn = (warp >> 1) * 32;
    const int bm = blockIdx.y, bn = blockIdx.x;

    const int row = tid >> 1;            // 0..127
    const int hs  = (tid & 1) * 16;      // halfs offset in 32-k tile
    const __half* Ag = Ah + (size_t)(bm * 128 + row) * K + hs;
    const __half* Bg = Bh + (size_t)(bn * 128 + row) * K + hs;
    const uint32_t sbase = (uint32_t)__cvta_generic_to_shared(smh);
    const uint32_t sAdst = sbase + row * 80 + hs * 2;
    const uint32_t sBdst = sbase + 10240 + row * 80 + hs * 2;

    float acc[4][4][4];
    #pragma unroll
    for (int i = 0; i < 4; i++)
        #pragma unroll
        for (int j = 0; j < 4; j++)
            #pragma unroll
            for (int r = 0; r < 4; r++) acc[i][j][r] = 0.f;

    const int ntiles = K >> 5;

    // preload tiles 0,1
    #pragma unroll
    for (int s = 0; s < 2; s++) {
        uint32_t off = s * STAGE_BYTES;
        cp_async16(sAdst + off,      Ag + s * 32);
        cp_async16(sAdst + off + 16, Ag + s * 32 + 8);
        cp_async16(sBdst + off,      Bg + s * 32);
        cp_async16(sBdst + off + 16, Bg + s * 32 + 8);
        CP_COMMIT();
    }

    int sidx = 0;
    for (int kt = 0; kt < ntiles; kt++) {
        CP_WAIT1();
        __syncthreads();

        if (kt + 2 < ntiles) {
            int s2 = sidx + 2; if (s2 >= 3) s2 -= 3;
            uint32_t off = s2 * STAGE_BYTES;
            const __half* Agk = Ag + (size_t)(kt + 2) * 32;
            const __half* Bgk = Bg + (size_t)(kt + 2) * 32;
            cp_async16(sAdst + off,      Agk);
            cp_async16(sAdst + off + 16, Agk + 8);
            cp_async16(sBdst + off,      Bgk);
            cp_async16(sBdst + off + 16, Bgk + 8);
        }
        CP_COMMIT();

        const __half* Ab = smh + sidx * (STAGE_BYTES / 2);
        const __half* Bb = Ab + 5120;
        #pragma unroll
        for (int ks = 0; ks < 2; ks++) {
            uint32_t af[4][4];
            uint32_t bf[4][2];
            #pragma unroll
            for (int mi = 0; mi < 4; mi++) {
                const __half* p = Ab + (wm + mi * 16 + g) * H_STRIDE + ks * 16 + 2 * tq;
                af[mi][0] = *(const uint32_t*)(p);
                af[mi][1] = *(const uint32_t*)(p + 8 * H_STRIDE);
                af[mi][2] = *(const uint32_t*)(p + 8);
                af[mi][3] = *(const uint32_t*)(p + 8 * H_STRIDE + 8);
            }
            #pragma unroll
            for (int nj = 0; nj < 4; nj++) {
                const __half* p = Bb + (wn + nj * 8 + g) * H_STRIDE + ks * 16 + 2 * tq;
                bf[nj][0] = *(const uint32_t*)(p);
                bf[nj][1] = *(const uint32_t*)(p + 8);
            }
            #pragma unroll
            for (int mi = 0; mi < 4; mi++)
                #pragma unroll
                for (int nj = 0; nj < 4; nj++)
                    mma_f16(acc[mi][nj], af[mi][0], af[mi][1], af[mi][2], af[mi][3],
                            bf[nj][0], bf[nj][1]);
        }

        sidx = (sidx + 1 < 3) ? sidx + 1 : 0;
    }

    // ---- epilogue ----
    const int row0 = bm * 128 + wm + g;
    const int col0 = bn * 128 + wn + 2 * tq;
    #pragma unroll
    for (int mi = 0; mi < 4; mi++) {
        #pragma unroll
        for (int nj = 0; nj < 4; nj++) {
            int c = col0 + nj * 8;
            float2 bvv = *(const float2*)(bias + c);
            #pragma unroll
            for (int half = 0; half < 2; half++) {
                int r = row0 + mi * 16 + half * 8;
                float v0 = acc[mi][nj][half * 2 + 0] + bvv.x;
                float v1 = acc[mi][nj][half * 2 + 1] + bvv.y;
                if (EPI == 0) {
                    float* cp = (float*)Cv + (size_t)r * N + c;
                    float2 w; w.x = v0; w.y = v1;
                    *(float2*)cp = w;
                } else if (EPI == 1) {
                    float* cp = (float*)Cv + (size_t)r * N + c;
                    float2 rv = *(const float2*)cp;
                    float2 w; w.x = v0 + rv.x; w.y = v1 + rv.y;
                    *(float2*)cp = w;
                } else {
                    v0 = 0.5f * v0 * (1.0f + erff(v0 * 0.70710678118654752f));
                    v1 = 0.5f * v1 * (1.0f + erff(v1 * 0.70710678118654752f));
                    __half* cp = (__half*)Cv + (size_t)r * N + c;
                    *(__half2*)cp = __floats2half2_rn(v0, v1);
                }
            }
        }
    }
}

// ------------------------- tensor-core flash attention (fp16 out) ------------
#define ATQ_STRIDE 76
#define ATKV_STRIDE 72
#define AQ_OFF   0
#define AP_OFF   (128 * ATQ_STRIDE)
#define AKV_OFF  (2 * 128 * ATQ_STRIDE)
#define ABIAS_OFF (AKV_OFF + 64 * ATKV_STRIDE)
#define ATT_SMEM_FLOATS (ABIAS_OFF + 512)

__global__ __launch_bounds__(256)
void attn_kernel(const float* __restrict__ t, const int* __restrict__ masked,
                 __half* __restrict__ o) {
    extern __shared__ float sm[];
    float* QS    = sm + AQ_OFF;    // [128][76]
    float* PS    = sm + AP_OFF;    // [128][76]
    float* KV    = sm + AKV_OFF;   // [64][72]
    float* biasS = sm + ABIAS_OFF; // [512]

    const int qt = blockIdx.x, h = blockIdx.y, b = blockIdx.z;
    const int tid = threadIdx.x;
    const int lane = tid & 31, w = tid >> 5;
    const int lq = lane >> 2, la = lane & 3;
    const int qr = w * 16;

    for (int i = tid; i < 512; i += 256)
        biasS[i] = (masked[b * 512 + i] == 1) ? -1e9f : 0.0f;

    {
        int row = tid >> 1;
        int c0  = (tid & 1) * 32;
        const float* qp = t + ((size_t)(b * 512 + qt * 128 + row)) * DD + h * 64 + c0;
        float* qs = QS + row * ATQ_STRIDE + c0;
        #pragma unroll
        for (int i = 0; i < 32; i += 4) {
            float4 v = *(const float4*)(qp + i);
            qs[i + 0] = to_tf32(v.x); qs[i + 1] = to_tf32(v.y);
            qs[i + 2] = to_tf32(v.z); qs[i + 3] = to_tf32(v.w);
        }
    }

    const float scale = 0.125f;
    float m0 = -1e30f, m1 = -1e30f, l0 = 0.f, l1 = 0.f;
    float oacc[8][4];
    #pragma unroll
    for (int nf = 0; nf < 8; nf++)
        #pragma unroll
        for (int r = 0; r < 4; r++) oacc[nf][r] = 0.f;

    for (int kt = 0; kt < 8; kt++) {
        __syncthreads();
        {
            int row = tid >> 2;
            int c0  = (tid & 3) * 16;
            const float* kp = t + ((size_t)(b * 512 + kt * 64 + row)) * DD + h * 64 + c0;
            float* ks = KV + row * ATKV_STRIDE + c0;
            #pragma unroll
            for (int i = 0; i < 16; i += 4) {
                float4 v = *(const float4*)(kp + i);
                ks[i + 0] = to_tf32(v.x); ks[i + 1] = to_tf32(v.y);
                ks[i + 2] = to_tf32(v.z); ks[i + 3] = to_tf32(v.w);
            }
        }
        __syncthreads();

        float s[8][4];
        #pragma unroll
        for (int nf = 0; nf < 8; nf++)
            #pragma unroll
            for (int r = 0; r < 4; r++) s[nf][r] = 0.f;

        #pragma unroll
        for (int kk = 0; kk < 8; kk++) {
            const float* ap = QS + (qr + lq) * ATQ_STRIDE + kk * 8 + la;
            uint32_t a0 = __float_as_uint(ap[0]);
            uint32_t a1 = __float_as_uint(ap[8 * ATQ_STRIDE]);
            uint32_t a2 = __float_as_uint(ap[4]);
            uint32_t a3 = __float_as_uint(ap[8 * ATQ_STRIDE + 4]);
            #pragma unroll
            for (int nf = 0; nf < 8; nf++) {
                const float* bp = KV + (nf * 8 + lq) * ATKV_STRIDE + kk * 8 + la;
                uint32_t b0 = __float_as_uint(bp[0]);
                uint32_t b1 = __float_as_uint(bp[4]);
                mma_tf32(s[nf], a0, a1, a2, a3, b0, b1);
            }
        }

        float tm0 = -1e30f, tm1 = -1e30f;
        #pragma unroll
        for (int nf = 0; nf < 8; nf++) {
            int c = kt * 64 + nf * 8 + 2 * la;
            float bv0 = biasS[c], bv1 = biasS[c + 1];
            s[nf][0] = s[nf][0] * scale + bv0;
            s[nf][1] = s[nf][1] * scale + bv1;
            s[nf][2] = s[nf][2] * scale + bv0;
            s[nf][3] = s[nf][3] * scale + bv1;
            tm0 = fmaxf(tm0, fmaxf(s[nf][0], s[nf][1]));
            tm1 = fmaxf(tm1, fmaxf(s[nf][2], s[nf][3]));
        }
        tm0 = fmaxf(tm0, __shfl_xor_sync(0xffffffffu, tm0, 1));
        tm0 = fmaxf(tm0, __shfl_xor_sync(0xffffffffu, tm0, 2));
        tm1 = fmaxf(tm1, __shfl_xor_sync(0xffffffffu, tm1, 1));
        tm1 = fmaxf(tm1, __shfl_xor_sync(0xffffffffu, tm1, 2));
        float mn0 = fmaxf(m0, tm0), mn1 = fmaxf(m1, tm1);
        float sc0 = __expf(m0 - mn0), sc1 = __expf(m1 - mn1);
        float ps0 = 0.f, ps1 = 0.f;
        float* pr0 = PS + (qr + lq) * ATQ_STRIDE + 2 * la;
        float* pr1 = PS + (qr + lq + 8) * ATQ_STRIDE + 2 * la;
        #pragma unroll
        for (int nf = 0; nf < 8; nf++) {
            float p0 = __expf(s[nf][0] - mn0);
            float p1 = __expf(s[nf][1] - mn0);
            float p2 = __expf(s[nf][2] - mn1);
            float p3 = __expf(s[nf][3] - mn1);
            ps0 += p0 + p1;
            ps1 += p2 + p3;
            pr0[nf * 8 + 0] = to_tf32(p0);
            pr0[nf * 8 + 1] = to_tf32(p1);
            pr1[nf * 8 + 0] = to_tf32(p2);
            pr1[nf * 8 + 1] = to_tf32(p3);
        }
        ps0 += __shfl_xor_sync(0xffffffffu, ps0, 1);
        ps0 += __shfl_xor_sync(0xffffffffu, ps0, 2);
        ps1 += __shfl_xor_sync(0xffffffffu, ps1, 1);
        ps1 += __shfl_xor_sync(0xffffffffu, ps1, 2);
        l0 = l0 * sc0 + ps0;
        l1 = l1 * sc1 + ps1;
        m0 = mn0; m1 = mn1;

        #pragma unroll
        for (int nf = 0; nf < 8; nf++) {
            oacc[nf][0] *= sc0; oacc[nf][1] *= sc0;
            oacc[nf][2] *= sc1; oacc[nf][3] *= sc1;
        }
        __syncwarp();

        #pragma unroll
        for (int kk = 0; kk < 8; kk++) {
            const float* ap = PS + (qr + lq) * ATQ_STRIDE + kk * 8 + la;
            uint32_t a0 = __float_as_uint(ap[0]);
            uint32_t a1 = __float_as_uint(ap[8 * ATQ_STRIDE]);
            uint32_t a2 = __float_as_uint(ap[4]);
            uint32_t a3 = __float_as_uint(ap[8 * ATQ_STRIDE + 4]);
            #pragma unroll
            for (int nf = 0; nf < 8; nf++) {
                const float* bp = KV + (kk * 8 + la) * ATKV_STRIDE + nf * 8 + lq;
                uint32_t b0 = __float_as_uint(bp[0]);
                uint32_t b1 = __float_as_uint(bp[4 * ATKV_STRIDE]);
                mma_tf32(oacc[nf], a0, a1, a2, a3, b0, b1);
            }
        }
    }

    float li0 = 1.0f / l0, li1 = 1.0f / l1;
    const size_t grow = (size_t)(b * 512 + qt * 128 + qr + lq);
    #pragma unroll
    for (int nf = 0; nf < 8; nf++) {
        int col = h * 64 + nf * 8 + 2 * la;
        *(__half2*)(o + grow * DD + col) =
            __floats2half2_rn(oacc[nf][0] * li0, oacc[nf][1] * li0);
        *(__half2*)(o + (grow + 8) * DD + col) =
            __floats2half2_rn(oacc[nf][2] * li1, oacc[nf][3] * li1);
    }
}

// ------------------------- host orchestration --------------------------------
extern "C" void kernel_launch(void* const* d_in, const int* in_sizes, int n_in,
                              void* d_out, int out_size) {
    const int*   masked = (const int*)  d_in[0];
    const float* tok    = (const float*)d_in[1];
    const float* seg    = (const float*)d_in[2];
    const float* ln1s   = (const float*)d_in[3];
    const float* ln1b   = (const float*)d_in[4];
    const float* wq     = (const float*)d_in[5];
    const float* bq     = (const float*)d_in[6];
    const float* wo     = (const float*)d_in[7];
    const float* bo     = (const float*)d_in[8];
    const float* ln2s   = (const float*)d_in[9];
    const float* ln2b   = (const float*)d_in[10];
    const float* w1     = (const float*)d_in[11];
    const float* b1     = (const float*)d_in[12];
    const float* w2     = (const float*)d_in[13];
    const float* b2     = (const float*)d_in[14];
    float* x = (float*)d_out;

    float* tt;
    __half *xh, *oh, *hh, *wh;
    cudaGetSymbolAddress((void**)&tt, g_t);
    cudaGetSymbolAddress((void**)&xh, g_xh);
    cudaGetSymbolAddress((void**)&oh, g_oh);
    cudaGetSymbolAddress((void**)&hh, g_hh);
    cudaGetSymbolAddress((void**)&wh, g_wh);

    const size_t ATT_SMEM = ATT_SMEM_FLOATS * sizeof(float);
    cudaFuncSetAttribute(attn_kernel, cudaFuncAttributeMaxDynamicSharedMemorySize,
                         (int)ATT_SMEM);
    cudaFuncSetAttribute(gemm_f16_kernel<0>, cudaFuncAttributeMaxDynamicSharedMemorySize,
                         GEMM16_SMEM_BYTES);
    cudaFuncSetAttribute(gemm_f16_kernel<1>, cudaFuncAttributeMaxDynamicSharedMemorySize,
                         GEMM16_SMEM_BYTES);
    cudaFuncSetAttribute(gemm_f16_kernel<2>, cudaFuncAttributeMaxDynamicSharedMemorySize,
                         GEMM16_SMEM_BYTES);

    // weight transposes (fp32 [K][N] -> fp16 [N][K], all layers)
    wtrans_kernel<<<dim3(DD / 32, DD / 32, LL), dim3(32, 8)>>>(wq, wh + WQ_OFF, DD, DD);
    wtrans_kernel<<<dim3(DD / 32, DD / 32, LL), dim3(32, 8)>>>(wo, wh + WO_OFF, DD, DD);
    wtrans_kernel<<<dim3(DFFN / 32, DD / 32, LL), dim3(32, 8)>>>(w1, wh + W1_OFF, DD, DFFN);
    wtrans_kernel<<<dim3(DD / 32, DFFN / 32, LL), dim3(32, 8)>>>(w2, wh + W2_OFF, DFFN, DD);

    embed_kernel<<<ROWS, 256>>>(masked, tok, seg, x);

    for (int l = 0; l < LL; l++) {
        const __half* wql = wh + WQ_OFF + (size_t)l * DD * DD;
        const __half* wol = wh + WO_OFF + (size_t)l * DD * DD;
        const __half* w1l = wh + W1_OFF + (size_t)l * DD * DFFN;
        const __half* w2l = wh + W2_OFF + (size_t)l * DFFN * DD;

        ln_kernel<<<ROWS / 8, 256>>>(x, ln1s + l * DD, ln1b + l * DD, xh);
        gemm_f16_kernel<0><<<dim3(DD / 128, ROWS / 128), 256, GEMM16_SMEM_BYTES>>>(
            xh, wql, bq + l * DD, tt, ROWS, DD, DD);
        attn_kernel<<<dim3(4, HH, BB), 256, ATT_SMEM>>>(tt, masked, oh);
        gemm_f16_kernel<1><<<dim3(DD / 128, ROWS / 128), 256, GEMM16_SMEM_BYTES>>>(
            oh, wol, bo + l * DD, x, ROWS, DD, DD);
        ln_kernel<<<ROWS / 8, 256>>>(x, ln2s + l * DD, ln2b + l * DD, xh);
        gemm_f16_kernel<2><<<dim3(DFFN / 128, ROWS / 128), 256, GEMM16_SMEM_BYTES>>>(
            xh, w1l, b1 + l * DFFN, hh, ROWS, DFFN, DD);
        gemm_f16_kernel<1><<<dim3(DD / 128, ROWS / 128), 256, GEMM16_SMEM_BYTES>>>(
            hh, w2l, b2 + l * DD, x, ROWS, DD, DFFN);
    }
}

// round 16
// speedup vs baseline: 2.7012x; 1.2754x over previous
#include <cuda_runtime.h>
#include <cuda_fp16.h>
#include <math.h>
#include <stdint.h>

#define BB 16
#define SS_ 512
#define DD 1024
#define HH 16
#define LL 12
#define DKK 64
#define DFFN 4096
#define ROWS (BB*SS_)   // 8192

// ------------------------- scratch (static device memory) -------------------
__device__ __half g_th[ROWS * DD];     // QKV projection t (fp16)
__device__ __half g_xh[ROWS * DD];     // LN output (fp16)
__device__ __half g_oh[ROWS * DD];     // attention output (fp16)
__device__ __half g_hh[ROWS * DFFN];   // FFN hidden (fp16)

// fp16 transposed weights [N][K] per layer
#define WQ_OFF 0
#define WO_OFF (12u * 1024u * 1024u)
#define W1_OFF (24u * 1024u * 1024u)
#define W2_OFF (72u * 1024u * 1024u)
__device__ __half g_wh[120u * 1024u * 1024u];

__device__ __forceinline__ void mma_f16(float c[4],
                                        uint32_t a0, uint32_t a1, uint32_t a2, uint32_t a3,
                                        uint32_t b0, uint32_t b1) {
    asm volatile(
        "mma.sync.aligned.m16n8k16.row.col.f32.f16.f16.f32 "
        "{%0,%1,%2,%3},{%4,%5,%6,%7},{%8,%9},{%0,%1,%2,%3};"
        : "+f"(c[0]), "+f"(c[1]), "+f"(c[2]), "+f"(c[3])
        : "r"(a0), "r"(a1), "r"(a2), "r"(a3), "r"(b0), "r"(b1));
}

__device__ __forceinline__ void ldsm_x4(uint32_t addr, uint32_t r[4]) {
    asm volatile("ldmatrix.sync.aligned.m8n8.x4.shared.b16 {%0,%1,%2,%3}, [%4];"
                 : "=r"(r[0]), "=r"(r[1]), "=r"(r[2]), "=r"(r[3]) : "r"(addr));
}

__device__ __forceinline__ void cp_async16(uint32_t saddr, const void* gptr) {
    asm volatile("cp.async.cg.shared.global [%0], [%1], 16;"
                 :: "r"(saddr), "l"(gptr) : "memory");
}
#define CP_COMMIT() asm volatile("cp.async.commit_group;" ::: "memory")
#define CP_WAIT1()  asm volatile("cp.async.wait_group 1;" ::: "memory")

// ------------------------- weight transpose fp32[K][N] -> fp16[N][K] --------
__global__ void wtrans_kernel(const float* __restrict__ src, __half* __restrict__ dst,
                              int K, int N) {
    __shared__ float t[32][33];
    const size_t lsz = (size_t)K * N;
    const float* s = src + blockIdx.z * lsz;
    __half* d = dst + blockIdx.z * lsz;
    int n0 = blockIdx.x * 32, k0 = blockIdx.y * 32;
    int tx = threadIdx.x, ty = threadIdx.y;
    #pragma unroll
    for (int i = 0; i < 4; i++)
        t[ty + 8 * i][tx] = s[(size_t)(k0 + ty + 8 * i) * N + n0 + tx];
    __syncthreads();
    #pragma unroll
    for (int i = 0; i < 4; i++)
        d[(size_t)(n0 + ty + 8 * i) * K + k0 + tx] = __float2half_rn(t[tx][ty + 8 * i]);
}

// ------------------------- embedding + positional encoding ------------------
__global__ void embed_kernel(const int* __restrict__ masked,
                             const float* __restrict__ tok,
                             const float* __restrict__ seg,
                             float* __restrict__ x) {
    int bs = blockIdx.x;
    int s  = bs & (SS_ - 1);
    int id = masked[bs];
    const float* tp = tok + (size_t)id * DD;
    const float* sp = seg + DD;          // seg_emb[1]
    int j = threadIdx.x * 4;
    const float L = 0.0089944730328f;    // ln(10000)/1024
    float f0 = expf(-(float)j * L);
    float f1 = expf(-(float)(j + 2) * L);
    float a0 = (float)s * f0;
    float a1 = (float)s * f1;
    float4 tv = *(const float4*)(tp + j);
    float4 sv = *(const float4*)(sp + j);
    float4 r;
    r.x = tv.x + sinf(a0) + sv.x;
    r.y = tv.y + cosf(a0) + sv.y;
    r.z = tv.z + sinf(a1) + sv.z;
    r.w = tv.w + cosf(a1) + sv.w;
    *(float4*)(x + (size_t)bs * DD + j) = r;
}

// ------------------------- layernorm (warp-per-row, fp16 out) ---------------
__global__ void ln_kernel(const float* __restrict__ x,
                          const float* __restrict__ gamma,
                          const float* __restrict__ beta,
                          __half* __restrict__ y) {
    const int row  = blockIdx.x * 8 + (threadIdx.x >> 5);
    const int lane = threadIdx.x & 31;
    const float4* xp = (const float4*)(x + (size_t)row * DD);
    float4 v[8];
    float s = 0.f, q = 0.f;
    #pragma unroll
    for (int i = 0; i < 8; i++) {
        v[i] = xp[lane + 32 * i];
        s += v[i].x + v[i].y + v[i].z + v[i].w;
        q += v[i].x * v[i].x + v[i].y * v[i].y + v[i].z * v[i].z + v[i].w * v[i].w;
    }
    #pragma unroll
    for (int o = 16; o > 0; o >>= 1) {
        s += __shfl_xor_sync(0xffffffffu, s, o);
        q += __shfl_xor_sync(0xffffffffu, q, o);
    }
    float m = s * (1.0f / DD);
    float r = rsqrtf(q * (1.0f / DD) - m * m + 1e-5f);
    const float4* gp = (const float4*)gamma;
    const float4* bp = (const float4*)beta;
    __half2* yp = (__half2*)(y + (size_t)row * DD);
    #pragma unroll
    for (int i = 0; i < 8; i++) {
        float4 g = gp[lane + 32 * i];
        float4 b = bp[lane + 32 * i];
        int e = (lane + 32 * i) * 2;
        yp[e + 0] = __floats2half2_rn((v[i].x - m) * r * g.x + b.x,
                                      (v[i].y - m) * r * g.y + b.y);
        yp[e + 1] = __floats2half2_rn((v[i].z - m) * r * g.z + b.z,
                                      (v[i].w - m) * r * g.w + b.w);
    }
}

// ------------------------- FP16 tensor-core GEMM (cp.async + ldmatrix) -------
// C[M,N] = Ah[M,K](fp16) * Bh[N,K](fp16 transposed), fp32 accum.
// CTA tile 128x128, k-tile 32 halfs, 8 warps, warp tile 64x32 via m16n8k16.
// 3-stage cp.async pipeline; fragment loads via ldmatrix.x4 (12 per tile/warp).
// EPI: 0 bias->fp32; 1 bias+residual fp32; 2 bias+GELU->fp16; 3 bias->fp16.
#define H_STRIDE 40
#define STAGE_BYTES 20480
#define GEMM16_SMEM_BYTES (3 * STAGE_BYTES)

template <int EPI>
__global__ __launch_bounds__(256, 2)
void gemm_f16_kernel(const __half* __restrict__ Ah, const __half* __restrict__ Bh,
                     const float* __restrict__ bias, void* __restrict__ Cv,
                     int M, int N, int K) {
    extern __shared__ __half smh[];
    const int tid  = threadIdx.x;
    const int lane = tid & 31;
    const int warp = tid >> 5;
    const int g = lane >> 2, tq = lane & 3;
    const int wm = (warp & 1) * 64;
    const int wn = (warp >> 1) * 32;
    const int bm = blockIdx.y, bn = blockIdx.x;

    const int row = tid >> 1;
    const int hs  = (tid & 1) * 16;
    const __half* Ag = Ah + (size_t)(bm * 128 + row) * K + hs;
    const __half* Bg = Bh + (size_t)(bn * 128 + row) * K + hs;
    const uint32_t sbase = (uint32_t)__cvta_generic_to_shared(smh);
    const uint32_t sAdst = sbase + row * 80 + hs * 2;
    const uint32_t sBdst = sbase + 10240 + row * 80 + hs * 2;

    // ldmatrix lane address selectors
    const int aSel = ((lane >> 3) & 1) * 8 + (lane & 7);
    const int aKh  = (lane >> 4) * 8;
    const int bSel = (lane >> 4) * 8 + (lane & 7);
    const int bKh  = ((lane >> 3) & 1) * 8;

    float acc[4][4][4];
    #pragma unroll
    for (int i = 0; i < 4; i++)
        #pragma unroll
        for (int j = 0; j < 4; j++)
            #pragma unroll
            for (int r = 0; r < 4; r++) acc[i][j][r] = 0.f;

    const int ntiles = K >> 5;

    #pragma unroll
    for (int s = 0; s < 2; s++) {
        uint32_t off = s * STAGE_BYTES;
        cp_async16(sAdst + off,      Ag + s * 32);
        cp_async16(sAdst + off + 16, Ag + s * 32 + 8);
        cp_async16(sBdst + off,      Bg + s * 32);
        cp_async16(sBdst + off + 16, Bg + s * 32 + 8);
        CP_COMMIT();
    }

    int sidx = 0;
    for (int kt = 0; kt < ntiles; kt++) {
        CP_WAIT1();
        __syncthreads();

        if (kt + 2 < ntiles) {
            int s2 = sidx + 2; if (s2 >= 3) s2 -= 3;
            uint32_t off = s2 * STAGE_BYTES;
            const __half* Agk = Ag + (size_t)(kt + 2) * 32;
            const __half* Bgk = Bg + (size_t)(kt + 2) * 32;
            cp_async16(sAdst + off,      Agk);
            cp_async16(sAdst + off + 16, Agk + 8);
            cp_async16(sBdst + off,      Bgk);
            cp_async16(sBdst + off + 16, Bgk + 8);
        }
        CP_COMMIT();

        const uint32_t aBase = sbase + sidx * STAGE_BYTES;
        const uint32_t bBase = aBase + 10240;
        #pragma unroll
        for (int ks = 0; ks < 2; ks++) {
            uint32_t af[4][4];
            uint32_t bf[4][2];
            #pragma unroll
            for (int mi = 0; mi < 4; mi++)
                ldsm_x4(aBase + (wm + mi * 16 + aSel) * 80 + (ks * 16 + aKh) * 2, af[mi]);
            #pragma unroll
            for (int p = 0; p < 2; p++) {
                uint32_t r4[4];
                ldsm_x4(bBase + (wn + p * 16 + bSel) * 80 + (ks * 16 + bKh) * 2, r4);
                bf[2 * p][0] = r4[0]; bf[2 * p][1] = r4[1];
                bf[2 * p + 1][0] = r4[2]; bf[2 * p + 1][1] = r4[3];
            }
            #pragma unroll
            for (int mi = 0; mi < 4; mi++)
                #pragma unroll
                for (int nj = 0; nj < 4; nj++)
                    mma_f16(acc[mi][nj], af[mi][0], af[mi][1], af[mi][2], af[mi][3],
                            bf[nj][0], bf[nj][1]);
        }

        sidx = (sidx + 1 < 3) ? sidx + 1 : 0;
    }

    // ---- epilogue ----
    const int row0 = bm * 128 + wm + g;
    const int col0 = bn * 128 + wn + 2 * tq;
    #pragma unroll
    for (int mi = 0; mi < 4; mi++) {
        #pragma unroll
        for (int nj = 0; nj < 4; nj++) {
            int c = col0 + nj * 8;
            float2 bvv = *(const float2*)(bias + c);
            #pragma unroll
            for (int half = 0; half < 2; half++) {
                int r = row0 + mi * 16 + half * 8;
                float v0 = acc[mi][nj][half * 2 + 0] + bvv.x;
                float v1 = acc[mi][nj][half * 2 + 1] + bvv.y;
                if (EPI == 0) {
                    float* cp = (float*)Cv + (size_t)r * N + c;
                    float2 w; w.x = v0; w.y = v1;
                    *(float2*)cp = w;
                } else if (EPI == 1) {
                    float* cp = (float*)Cv + (size_t)r * N + c;
                    float2 rv = *(const float2*)cp;
                    float2 w; w.x = v0 + rv.x; w.y = v1 + rv.y;
                    *(float2*)cp = w;
                } else if (EPI == 2) {
                    v0 = 0.5f * v0 * (1.0f + erff(v0 * 0.70710678118654752f));
                    v1 = 0.5f * v1 * (1.0f + erff(v1 * 0.70710678118654752f));
                    __half* cp = (__half*)Cv + (size_t)r * N + c;
                    *(__half2*)cp = __floats2half2_rn(v0, v1);
                } else {
                    __half* cp = (__half*)Cv + (size_t)r * N + c;
                    *(__half2*)cp = __floats2half2_rn(v0, v1);
                }
            }
        }
    }
}

// ------------------------- fp16 tensor-core flash attention ------------------
// CTA 256 threads / 8 warps; 128 q-rows; grid (4, H, B). Streams 8 kv-tiles.
// All operands fp16 (m16n8k16), fp32 accum. smem (halfs, stride 72):
// QS[128][72], PS[128][72], K[64][72] ([key][d]), VT[64][72] ([d][key]), bias f32[512].
#define AH_STRIDE 72
#define AQS_OFF 0
#define APS_OFF (128 * AH_STRIDE)
#define AK_OFF  (2 * 128 * AH_STRIDE)
#define AVT_OFF (AK_OFF + 64 * AH_STRIDE)
#define ABF_OFF (AVT_OFF + 64 * AH_STRIDE)       // float bias at half-offset
#define ATT_SMEM_BYTES ((ABF_OFF) * 2 + 512 * 4)

__global__ __launch_bounds__(256)
void attn_kernel(const __half* __restrict__ t, const int* __restrict__ masked,
                 __half* __restrict__ o) {
    extern __shared__ __half smh[];
    __half* QS  = smh + AQS_OFF;
    __half* PS  = smh + APS_OFF;
    __half* Kh  = smh + AK_OFF;
    __half* VT  = smh + AVT_OFF;
    float* biasS = (float*)(smh + ABF_OFF);

    const int qt = blockIdx.x, h = blockIdx.y, b = blockIdx.z;
    const int tid = threadIdx.x;
    const int lane = tid & 31, w = tid >> 5;
    const int lq = lane >> 2, la = lane & 3;
    const int tq = la;
    const int qr = w * 16;

    for (int i = tid; i < 512; i += 256)
        biasS[i] = (masked[b * 512 + i] == 1) ? -1e9f : 0.0f;

    // Q tile (128 x 64 halfs)
    {
        int row = tid >> 1;
        int c0  = (tid & 1) * 32;
        const __half* qp = t + ((size_t)(b * 512 + qt * 128 + row)) * DD + h * 64 + c0;
        __half* qs = QS + row * AH_STRIDE + c0;
        #pragma unroll
        for (int i = 0; i < 4; i++)
            *(uint4*)(qs + i * 8) = *(const uint4*)(qp + i * 8);
    }

    const float scale = 0.125f;
    float m0 = -1e30f, m1 = -1e30f, l0 = 0.f, l1 = 0.f;
    float oacc[8][4];
    #pragma unroll
    for (int nf = 0; nf < 8; nf++)
        #pragma unroll
        for (int r = 0; r < 4; r++) oacc[nf][r] = 0.f;

    for (int kt = 0; kt < 8; kt++) {
        __syncthreads();
        // KV tile: K [key][d] + VT [d][key]
        {
            int row = tid >> 2;              // key 0..63
            int d0  = (tid & 3) * 16;
            const __half* kp = t + ((size_t)(b * 512 + kt * 64 + row)) * DD + h * 64 + d0;
            uint4 u0 = *(const uint4*)(kp);
            uint4 u1 = *(const uint4*)(kp + 8);
            *(uint4*)(Kh + row * AH_STRIDE + d0)     = u0;
            *(uint4*)(Kh + row * AH_STRIDE + d0 + 8) = u1;
            const __half* hv = (const __half*)&u0;
            #pragma unroll
            for (int j = 0; j < 8; j++) VT[(d0 + j) * AH_STRIDE + row] = hv[j];
            hv = (const __half*)&u1;
            #pragma unroll
            for (int j = 0; j < 8; j++) VT[(d0 + 8 + j) * AH_STRIDE + row] = hv[j];
        }
        __syncthreads();

        // ---- scores: S(16x64) = Q_w . K^T, 4 k16-steps x 8 n-frags ----
        float s[8][4];
        #pragma unroll
        for (int nf = 0; nf < 8; nf++)
            #pragma unroll
            for (int r = 0; r < 4; r++) s[nf][r] = 0.f;

        #pragma unroll
        for (int ks = 0; ks < 4; ks++) {
            const __half* ap = QS + (qr + lq) * AH_STRIDE + ks * 16 + 2 * tq;
            uint32_t a0 = *(const uint32_t*)(ap);
            uint32_t a1 = *(const uint32_t*)(ap + 8 * AH_STRIDE);
            uint32_t a2 = *(const uint32_t*)(ap + 8);
            uint32_t a3 = *(const uint32_t*)(ap + 8 * AH_STRIDE + 8);
            #pragma unroll
            for (int nf = 0; nf < 8; nf++) {
                const __half* bp = Kh + (nf * 8 + lq) * AH_STRIDE + ks * 16 + 2 * tq;
                uint32_t b0 = *(const uint32_t*)(bp);
                uint32_t b1 = *(const uint32_t*)(bp + 8);
                mma_f16(s[nf], a0, a1, a2, a3, b0, b1);
            }
        }

        // ---- scale + bias + online softmax (quad-local) ----
        float tm0 = -1e30f, tm1 = -1e30f;
        #pragma unroll
        for (int nf = 0; nf < 8; nf++) {
            int c = kt * 64 + nf * 8 + 2 * la;
            float bv0 = biasS[c], bv1 = biasS[c + 1];
            s[nf][0] = s[nf][0] * scale + bv0;
            s[nf][1] = s[nf][1] * scale + bv1;
            s[nf][2] = s[nf][2] * scale + bv0;
            s[nf][3] = s[nf][3] * scale + bv1;
            tm0 = fmaxf(tm0, fmaxf(s[nf][0], s[nf][1]));
            tm1 = fmaxf(tm1, fmaxf(s[nf][2], s[nf][3]));
        }
        tm0 = fmaxf(tm0, __shfl_xor_sync(0xffffffffu, tm0, 1));
        tm0 = fmaxf(tm0, __shfl_xor_sync(0xffffffffu, tm0, 2));
        tm1 = fmaxf(tm1, __shfl_xor_sync(0xffffffffu, tm1, 1));
        tm1 = fmaxf(tm1, __shfl_xor_sync(0xffffffffu, tm1, 2));
        float mn0 = fmaxf(m0, tm0), mn1 = fmaxf(m1, tm1);
        float sc0 = __expf(m0 - mn0), sc1 = __expf(m1 - mn1);
        float ps0 = 0.f, ps1 = 0.f;
        __half* pr0 = PS + (qr + lq) * AH_STRIDE + 2 * la;
        __half* pr1 = PS + (qr + lq + 8) * AH_STRIDE + 2 * la;
        #pragma unroll
        for (int nf = 0; nf < 8; nf++) {
            float p0 = __expf(s[nf][0] - mn0);
            float p1 = __expf(s[nf][1] - mn0);
            float p2 = __expf(s[nf][2] - mn1);
            float p3 = __expf(s[nf][3] - mn1);
            ps0 += p0 + p1;
            ps1 += p2 + p3;
            *(__half2*)(pr0 + nf * 8) = __floats2half2_rn(p0, p1);
            *(__half2*)(pr1 + nf * 8) = __floats2half2_rn(p2, p3);
        }
        ps0 += __shfl_xor_sync(0xffffffffu, ps0, 1);
        ps0 += __shfl_xor_sync(0xffffffffu, ps0, 2);
        ps1 += __shfl_xor_sync(0xffffffffu, ps1, 1);
        ps1 += __shfl_xor_sync(0xffffffffu, ps1, 2);
        l0 = l0 * sc0 + ps0;
        l1 = l1 * sc1 + ps1;
        m0 = mn0; m1 = mn1;

        #pragma unroll
        for (int nf = 0; nf < 8; nf++) {
            oacc[nf][0] *= sc0; oacc[nf][1] *= sc0;
            oacc[nf][2] *= sc1; oacc[nf][3] *= sc1;
        }
        __syncwarp();

        // ---- PV: O(16x64) += P_w . V, B = VT[d][key] ----
        #pragma unroll
        for (int ks = 0; ks < 4; ks++) {
            const __half* ap = PS + (qr + lq) * AH_STRIDE + ks * 16 + 2 * tq;
            uint32_t a0 = *(const uint32_t*)(ap);
            uint32_t a1 = *(const uint32_t*)(ap + 8 * AH_STRIDE);
            uint32_t a2 = *(const uint32_t*)(ap + 8);
            uint32_t a3 = *(const uint32_t*)(ap + 8 * AH_STRIDE + 8);
            #pragma unroll
            for (int nf = 0; nf < 8; nf++) {
                const __half* bp = VT + (nf * 8 + lq) * AH_STRIDE + ks * 16 + 2 * tq;
                uint32_t b0 = *(const uint32_t*)(bp);
                uint32_t b1 = *(const uint32_t*)(bp + 8);
                mma_f16(oacc[nf], a0, a1, a2, a3, b0, b1);
            }
        }
    }

    float li0 = 1.0f / l0, li1 = 1.0f / l1;
    const size_t grow = (size_t)(b * 512 + qt * 128 + qr + lq);
    #pragma unroll
    for (int nf = 0; nf < 8; nf++) {
        int col = h * 64 + nf * 8 + 2 * la;
        *(__half2*)(o + grow * DD + col) =
            __floats2half2_rn(oacc[nf][0] * li0, oacc[nf][1] * li0);
        *(__half2*)(o + (grow + 8) * DD + col) =
            __floats2half2_rn(oacc[nf][2] * li1, oacc[nf][3] * li1);
    }
}

// ------------------------- host orchestration --------------------------------
extern "C" void kernel_launch(void* const* d_in, const int* in_sizes, int n_in,
                              void* d_out, int out_size) {
    const int*   masked = (const int*)  d_in[0];
    const float* tok    = (const float*)d_in[1];
    const float* seg    = (const float*)d_in[2];
    const float* ln1s   = (const float*)d_in[3];
    const float* ln1b   = (const float*)d_in[4];
    const float* wq     = (const float*)d_in[5];
    const float* bq     = (const float*)d_in[6];
    const float* wo     = (const float*)d_in[7];
    const float* bo     = (const float*)d_in[8];
    const float* ln2s   = (const float*)d_in[9];
    const float* ln2b   = (const float*)d_in[10];
    const float* w1     = (const float*)d_in[11];
    const float* b1     = (const float*)d_in[12];
    const float* w2     = (const float*)d_in[13];
    const float* b2     = (const float*)d_in[14];
    float* x = (float*)d_out;

    __half *th, *xh, *oh, *hh, *wh;
    cudaGetSymbolAddress((void**)&th, g_th);
    cudaGetSymbolAddress((void**)&xh, g_xh);
    cudaGetSymbolAddress((void**)&oh, g_oh);
    cudaGetSymbolAddress((void**)&hh, g_hh);
    cudaGetSymbolAddress((void**)&wh, g_wh);

    cudaFuncSetAttribute(attn_kernel, cudaFuncAttributeMaxDynamicSharedMemorySize,
                         ATT_SMEM_BYTES);
    cudaFuncSetAttribute(gemm_f16_kernel<1>, cudaFuncAttributeMaxDynamicSharedMemorySize,
                         GEMM16_SMEM_BYTES);
    cudaFuncSetAttribute(gemm_f16_kernel<2>, cudaFuncAttributeMaxDynamicSharedMemorySize,
                         GEMM16_SMEM_BYTES);
    cudaFuncSetAttribute(gemm_f16_kernel<3>, cudaFuncAttributeMaxDynamicSharedMemorySize,
                         GEMM16_SMEM_BYTES);

    // weight transposes (fp32 [K][N] -> fp16 [N][K], all layers)
    wtrans_kernel<<<dim3(DD / 32, DD / 32, LL), dim3(32, 8)>>>(wq, wh + WQ_OFF, DD, DD);
    wtrans_kernel<<<dim3(DD / 32, DD / 32, LL), dim3(32, 8)>>>(wo, wh + WO_OFF, DD, DD);
    wtrans_kernel<<<dim3(DFFN / 32, DD / 32, LL), dim3(32, 8)>>>(w1, wh + W1_OFF, DD, DFFN);
    wtrans_kernel<<<dim3(DD / 32, DFFN / 32, LL), dim3(32, 8)>>>(w2, wh + W2_OFF, DFFN, DD);

    embed_kernel<<<ROWS, 256>>>(masked, tok, seg, x);

    for (int l = 0; l < LL; l++) {
        const __half* wql = wh + WQ_OFF + (size_t)l * DD * DD;
        const __half* wol = wh + WO_OFF + (size_t)l * DD * DD;
        const __half* w1l = wh + W1_OFF + (size_t)l * DD * DFFN;
        const __half* w2l = wh + W2_OFF + (size_t)l * DFFN * DD;

        ln_kernel<<<ROWS / 8, 256>>>(x, ln1s + l * DD, ln1b + l * DD, xh);
        gemm_f16_kernel<3><<<dim3(DD / 128, ROWS / 128), 256, GEMM16_SMEM_BYTES>>>(
            xh, wql, bq + l * DD, th, ROWS, DD, DD);
        attn_kernel<<<dim3(4, HH, BB), 256, ATT_SMEM_BYTES>>>(th, masked, oh);
        gemm_f16_kernel<1><<<dim3(DD / 128, ROWS / 128), 256, GEMM16_SMEM_BYTES>>>(
            oh, wol, bo + l * DD, x, ROWS, DD, DD);
        ln_kernel<<<ROWS / 8, 256>>>(x, ln2s + l * DD, ln2b + l * DD, xh);
        gemm_f16_kernel<2><<<dim3(DFFN / 128, ROWS / 128), 256, GEMM16_SMEM_BYTES>>>(
            xh, w1l, b1 + l * DFFN, hh, ROWS, DFFN, DD);
        gemm_f16_kernel<1><<<dim3(DD / 128, ROWS / 128), 256, GEMM16_SMEM_BYTES>>>(
            hh, w2l, b2 + l * DD, x, ROWS, DD, DFFN);
    }
}